// round 15
// baseline (speedup 1.0000x reference)
#include <cuda_runtime.h>
#include <cuda_fp16.h>
#include <cstdint>

#define UNITS   256
#define G3      768
#define NROWS   32
#define NCTA    128
#define NTHREADS 512
#define TSTEPS  191
#define WARM    64

#define L1_SLABS 17
#define L2_SLABS 32
#define L1_U4   (L1_SLABS*1536)
#define L2_U4   (L2_SLABS*1536)
#define TOT_U4  (L1_U4 + L2_U4)

__device__ uint4 g_wts[TOT_U4];  // fp16 blobs, fragment-ordered for m16n8k16

#define SZ_HA1  (2*L1_SLABS*32*4)
#define OFF_HA1 0
#define OFF_HA2 (OFF_HA1 + 2*SZ_HA1)
#define SZ_HA2  (2*16*32*4)
#define OFF_BM1 (OFF_HA2 + SZ_HA2)
#define OFF_BM2 (OFF_BM1 + 1024)
#define OFF_WD  (OFF_BM2 + 1024)
#define OFF_BD  (OFF_WD + UNITS*5)
#define OFF_PART (OFF_BD + 8)
#define OFF_QP  (OFF_PART + 16*160)
#define SMEM_FLOATS (OFF_QP + NROWS*127)
#define SMEM_BYTES  (SMEM_FLOATS*4)

__device__ __forceinline__ uint32_t pack2(float lo, float hi){
    __half2 h = __floats2half2_rn(lo, hi);
    return *(uint32_t*)&h;
}
__device__ __forceinline__ void mma_h(float (&c)[4], const uint4& a, uint32_t b0, uint32_t b1){
    asm volatile(
        "mma.sync.aligned.m16n8k16.row.col.f32.f16.f16.f32 "
        "{%0,%1,%2,%3},{%4,%5,%6,%7},{%8,%9},{%0,%1,%2,%3};\n"
        : "+f"(c[0]), "+f"(c[1]), "+f"(c[2]), "+f"(c[3])
        : "r"(a.x), "r"(a.y), "r"(a.z), "r"(a.w), "r"(b0), "r"(b1));
}
__device__ __forceinline__ float tanh_ap(float x){
    float y; asm("tanh.approx.f32 %0, %1;" : "=f"(y) : "f"(x)); return y;
}
__device__ __forceinline__ float sigf(float x){
    return fmaf(tanh_ap(0.5f*x), 0.5f, 0.5f);
}

#define MMA_GATE(ACC, B4, a0, a1) do {                     \
    mma_h(ACC[0][0], a0, (B4).x, (B4).y);                  \
    mma_h(ACC[1][0], a1, (B4).x, (B4).y);                  \
    mma_h(ACC[0][1], a0, (B4).z, (B4).w);                  \
    mma_h(ACC[1][1], a1, (B4).z, (B4).w);                  \
} while (0)

#define ZERO_ACC do {                                      \
    _Pragma("unroll")                                      \
    for (int m_=0;m_<2;m_++) _Pragma("unroll")             \
    for (int t_=0;t_<2;t_++) _Pragma("unroll")             \
    for (int c_=0;c_<4;c_++){                              \
        az[m_][t_][c_]=0.f; ar[m_][t_][c_]=0.f;            \
        axh[m_][t_][c_]=0.f; arh[m_][t_][c_]=0.f; }        \
} while (0)

#define PF_STEP(CZ,CR,CH,Bn) \
    uint4 CZ = pbz0, CR = pbr0, CH = pbh0;                  \
    pbz0 = pbz1; pbr0 = pbr1; pbh0 = pbh1;                  \
    pbz1 = __ldg(Bn); pbr1 = __ldg((Bn)+512); pbh1 = __ldg((Bn)+1024);

// ---------------------------------------------------------------------------
__global__ void prep_kernel(const float* __restrict__ W1, const float* __restrict__ U1,
                            const float* __restrict__ W2, const float* __restrict__ U2){
    for (int idx = blockIdx.x*blockDim.x + threadIdx.x; idx < TOT_U4;
         idx += gridDim.x*blockDim.x){
        int li   = (idx < L1_U4) ? idx : idx - L1_U4;
        int lane = li & 31;
        int w    = (li >> 5) & 7;
        int t2   = (li >> 8) & 1;
        int g    = (li >> 9) % 3;
        int slab = (li >> 9) / 3;
        int lc = lane & 3, lr = lane >> 2;
        uint32_t v[4];
        #pragma unroll
        for (int j = 0; j < 4; j++){
            int q  = j & 1;
            int tt = t2*2 + (j >> 1);
            int col = g*256 + w*32 + tt*8 + lr;
            int kl  = 2*lc + 8*q;
            float s0, s1;
            if (idx < L1_U4){
                if (slab < 16){
                    s0 = U1[(slab*16 + kl)*G3 + col];
                    s1 = U1[(slab*16 + kl + 1)*G3 + col];
                } else {
                    s0 = (kl     < 6) ? W1[kl*G3 + col]       : 0.f;
                    s1 = (kl + 1 < 6) ? W1[(kl + 1)*G3 + col] : 0.f;
                }
            } else {
                if (slab < 16){
                    s0 = W2[(slab*16 + kl)*G3 + col];
                    s1 = W2[(slab*16 + kl + 1)*G3 + col];
                } else {
                    s0 = U2[((slab-16)*16 + kl)*G3 + col];
                    s1 = U2[((slab-16)*16 + kl + 1)*G3 + col];
                }
            }
            v[j] = pack2(s0, s1);
        }
        g_wts[idx] = make_uint4(v[0], v[1], v[2], v[3]);
    }
}

// ---------------------------------------------------------------------------
__global__ void __launch_bounds__(NTHREADS, 1)
gru_kernel(const float* __restrict__ inputs, const float* __restrict__ gb1,
           const float* __restrict__ gb2, const float* __restrict__ gWd,
           const float* __restrict__ gbd, float* __restrict__ out){
    extern __shared__ __align__(16) float sm[];
    float* bm1 = sm + OFF_BM1;
    float* bm2 = sm + OFF_BM2;
    float* wds = sm + OFF_WD;
    float* bds = sm + OFF_BD;
    float* part= sm + OFF_PART;
    float* qpre= sm + OFF_QP;

    const int tid  = threadIdx.x;
    const int lane = tid & 31;
    const int warp = tid >> 5;
    const int lr   = lane >> 2;
    const int lc   = lane & 3;
    const int u0   = warp * 16;
    const int row0 = blockIdx.x * NROWS;
    const int wB   = ((warp & 1) << 8) + ((warp >> 1) << 5) + lane;

    // merged biases: [0:256)=z, [256:512)=r, [512:768)=xh, [768:1024)=rh
    for (int i = tid; i < 256; i += NTHREADS){
        bm1[i]       = gb1[i]       + gb1[G3 + i];
        bm1[256 + i] = gb1[256 + i] + gb1[G3 + 256 + i];
        bm1[512 + i] = gb1[512 + i];
        bm1[768 + i] = gb1[G3 + 512 + i];
        bm2[i]       = gb2[i]       + gb2[G3 + i];
        bm2[256 + i] = gb2[256 + i] + gb2[G3 + 256 + i];
        bm2[512 + i] = gb2[512 + i];
        bm2[768 + i] = gb2[G3 + 512 + i];
    }
    for (int i = tid; i < UNITS*5; i += NTHREADS) wds[i] = gWd[i];
    if (tid < 5) bds[tid] = gbd[tid];
    for (int i = tid; i < 2*SZ_HA1; i += NTHREADS) sm[OFF_HA1 + i] = 0.f;
    for (int i = tid; i < SZ_HA2;   i += NTHREADS) sm[OFF_HA2 + i] = 0.f;
    for (int i = tid; i < NROWS*127; i += NTHREADS){
        int row = i / 127, s = i % 127;
        qpre[i] = inputs[((size_t)(row0 + row)*192 + WARM + s)*6];
    }
    __syncthreads();

    // stage x_0 into buffer 0, slab 16
    if (tid < NROWS){
        int row = tid;
        const float* ip = inputs + ((size_t)(row0 + row)*192 + 0)*6;
        int m = row >> 4, rr = row & 15, hh = rr >> 3, rl = rr & 7;
        __half* hp = (__half*)(sm + OFF_HA1);
        #pragma unroll
        for (int k = 0; k < 6; k++)
            hp[(((m*L1_SLABS + 16)*32 + rl*4 + (k >> 1))*4 + hh)*2 + (k & 1)]
                = __float2half_rn(ip[k]);
    }
    __syncthreads();

    const uint4* hA2u = (const uint4*)(sm + OFF_HA2);
    const uint4* B1b  = g_wts + wB;
    const uint4* B2b  = g_wts + L1_U4 + wB;

    float az[2][2][4], ar[2][2][4], axh[2][2][4], arh[2][2][4];
    float h1s[16], h2s[16];        // per-layer state, exact fp32, thread-private
    #pragma unroll
    for (int i = 0; i < 16; i++){ h1s[i] = 0.f; h2s[i] = 0.f; }
    #define HIDX(m,tt,hi,cc) ((((m)*2+(tt))*2+(hi))*2+(cc))

    uint4 pbz0 = __ldg(B1b),        pbr0 = __ldg(B1b + 512),        pbh0 = __ldg(B1b + 1024);
    uint4 pbz1 = __ldg(B1b + 1536), pbr1 = __ldg(B1b + 1536 + 512), pbh1 = __ldg(B1b + 1536 + 1024);

    for (int t = 0; t < TSTEPS; t++){
        const int p = t & 1;
        const uint4* hAr = (const uint4*)(sm + OFF_HA1 + p*SZ_HA1);
        float*       hWf = sm + OFF_HA1 + (1-p)*SZ_HA1;
        const uint4* hAw = (const uint4*)hWf;

        // ===== GEMM1: h1_old @ U1 (slabs 0..15) + x (slab 16) =====
        ZERO_ACC;
        #pragma unroll 4
        for (int s = 0; s < 16; s++){
            uint4 a0 = hAr[s*32 + lane];
            uint4 a1 = hAr[(L1_SLABS + s)*32 + lane];
            const uint4* Bn = (s <= 14) ? (B1b + (s+2)*1536) : (B2b + 16*1536);
            PF_STEP(cz, cr, ch, Bn);
            MMA_GATE(az,  cz, a0, a1);
            MMA_GATE(ar,  cr, a0, a1);
            MMA_GATE(arh, ch, a0, a1);
        }
        {
            uint4 a0 = hAr[16*32 + lane];
            uint4 a1 = hAr[(L1_SLABS + 16)*32 + lane];
            const uint4* Bn = B2b + 17*1536;
            PF_STEP(cz, cr, ch, Bn);
            MMA_GATE(az,  cz, a0, a1);
            MMA_GATE(ar,  cr, a0, a1);
            MMA_GATE(axh, ch, a0, a1);
        }

        // ---- gate 1 (register state) + inline h1_new A-store ----
        {
            uint32_t* wp = (uint32_t*)hWf;
            #pragma unroll
            for (int tt = 0; tt < 2; tt++){
                int uc0 = u0 + tt*8 + 2*lc, uc1 = uc0 + 1;
                float bz0 = bm1[uc0],       bz1 = bm1[uc1];
                float br0 = bm1[256 + uc0], br1 = bm1[256 + uc1];
                float bx0 = bm1[512 + uc0], bx1 = bm1[512 + uc1];
                float bh0 = bm1[768 + uc0], bh1 = bm1[768 + uc1];
                #pragma unroll
                for (int m = 0; m < 2; m++)
                    #pragma unroll
                    for (int hi = 0; hi < 2; hi++){
                        int c0 = hi*2, c1 = hi*2 + 1;
                        float z0 = sigf(az[m][tt][c0] + bz0);
                        float r0 = sigf(ar[m][tt][c0] + br0);
                        float g0 = tanh_ap(axh[m][tt][c0] + bx0 + r0*(arh[m][tt][c0] + bh0));
                        float v0 = z0*h1s[HIDX(m,tt,hi,0)] + (1.f - z0)*g0;
                        h1s[HIDX(m,tt,hi,0)] = v0;
                        float z1 = sigf(az[m][tt][c1] + bz1);
                        float r1 = sigf(ar[m][tt][c1] + br1);
                        float g1 = tanh_ap(axh[m][tt][c1] + bx1 + r1*(arh[m][tt][c1] + bh1));
                        float v1 = z1*h1s[HIDX(m,tt,hi,1)] + (1.f - z1)*g1;
                        h1s[HIDX(m,tt,hi,1)] = v1;
                        wp[((m*L1_SLABS + warp)*32 + lr*4 + lc)*4 + tt*2 + hi]
                            = pack2(v0, v1);
                    }
            }
        }

        // ===== GEMM2a: h2_old @ U2 (L2 blob slabs 16..31) =====
        ZERO_ACC;
        #pragma unroll 4
        for (int s = 0; s < 16; s++){
            uint4 a0 = hA2u[s*32 + lane];
            uint4 a1 = hA2u[(16 + s)*32 + lane];
            const uint4* Bn = (s <= 13) ? (B2b + (18 + s)*1536)
                             : ((s == 14) ? B2b : (B2b + 1536));
            PF_STEP(cz, cr, ch, Bn);
            MMA_GATE(az,  cz, a0, a1);
            MMA_GATE(ar,  cr, a0, a1);
            MMA_GATE(arh, ch, a0, a1);
        }
        __syncthreads();                       // B1: h1_new visible

        // ===== GEMM2b: h1_new @ W2 (L2 blob slabs 0..15) =====
        #pragma unroll 4
        for (int s = 0; s < 16; s++){
            uint4 a0 = hAw[s*32 + lane];
            uint4 a1 = hAw[(L1_SLABS + s)*32 + lane];
            const uint4* Bn = (s <= 13) ? (B2b + (s+2)*1536)
                             : ((s == 14) ? B1b : (B1b + 1536));
            PF_STEP(cz, cr, ch, Bn);
            MMA_GATE(az,  cz, a0, a1);
            MMA_GATE(ar,  cr, a0, a1);
            MMA_GATE(axh, ch, a0, a1);
        }

        // ---- gate 2 (register state) + inline h2 A-store + pred partials ----
        float ps[4][5];
        #pragma unroll
        for (int ri = 0; ri < 4; ri++)
            #pragma unroll
            for (int o = 0; o < 5; o++) ps[ri][o] = 0.f;
        {
            uint32_t* wp = (uint32_t*)(sm + OFF_HA2);
            #pragma unroll
            for (int tt = 0; tt < 2; tt++){
                int uc0 = u0 + tt*8 + 2*lc, uc1 = uc0 + 1;
                float bz0 = bm2[uc0],       bz1 = bm2[uc1];
                float br0 = bm2[256 + uc0], br1 = bm2[256 + uc1];
                float bx0 = bm2[512 + uc0], bx1 = bm2[512 + uc1];
                float bh0 = bm2[768 + uc0], bh1 = bm2[768 + uc1];
                float wd0[5], wd1[5];
                #pragma unroll
                for (int o = 0; o < 5; o++){ wd0[o] = wds[uc0*5 + o]; wd1[o] = wds[uc1*5 + o]; }
                #pragma unroll
                for (int m = 0; m < 2; m++)
                    #pragma unroll
                    for (int hi = 0; hi < 2; hi++){
                        int c0 = hi*2, c1 = hi*2 + 1;
                        float z0 = sigf(az[m][tt][c0] + bz0);
                        float r0 = sigf(ar[m][tt][c0] + br0);
                        float g0 = tanh_ap(axh[m][tt][c0] + bx0 + r0*(arh[m][tt][c0] + bh0));
                        float v0 = z0*h2s[HIDX(m,tt,hi,0)] + (1.f - z0)*g0;
                        h2s[HIDX(m,tt,hi,0)] = v0;
                        float z1 = sigf(az[m][tt][c1] + bz1);
                        float r1 = sigf(ar[m][tt][c1] + br1);
                        float g1 = tanh_ap(axh[m][tt][c1] + bx1 + r1*(arh[m][tt][c1] + bh1));
                        float v1 = z1*h2s[HIDX(m,tt,hi,1)] + (1.f - z1)*g1;
                        h2s[HIDX(m,tt,hi,1)] = v1;
                        wp[((m*16 + warp)*32 + lr*4 + lc)*4 + tt*2 + hi]
                            = pack2(v0, v1);
                        int ri = 2*m + hi;
                        #pragma unroll
                        for (int o = 0; o < 5; o++)
                            ps[ri][o] += v0*wd0[o] + v1*wd1[o];
                    }
            }
        }
        #pragma unroll
        for (int ri = 0; ri < 4; ri++)
            #pragma unroll
            for (int o = 0; o < 5; o++){
                ps[ri][o] += __shfl_xor_sync(0xffffffffu, ps[ri][o], 1);
                ps[ri][o] += __shfl_xor_sync(0xffffffffu, ps[ri][o], 2);
            }
        if (lc == 0){
            #pragma unroll
            for (int ri = 0; ri < 4; ri++)
                #pragma unroll
                for (int o = 0; o < 5; o++)
                    part[warp*160 + (lr + 8*ri)*5 + o] = ps[ri][o];
        }
        __syncthreads();                       // B2

        // ---- tail: reduce, output, stage x_{t+1} ----
        if (tid < 160){
            int row = tid / 5, o = tid % 5;
            float s = bds[o];
            #pragma unroll
            for (int w = 0; w < 16; w++) s += part[w*160 + tid];
            int grow = row0 + row;
            int tout = (t < WARM) ? t : t + 1;
            out[(size_t)grow*960 + tout*5 + o] = s;
            if (t == WARM - 1) out[(size_t)grow*960 + WARM*5 + o] = s;
            if (t + 1 >= WARM && t + 1 < TSTEPS){
                int k = o + 1;
                int m = row >> 4, rr = row & 15, hh = rr >> 3, rl = rr & 7;
                __half* hp = (__half*)hWf;
                hp[(((m*L1_SLABS + 16)*32 + rl*4 + (k >> 1))*4 + hh)*2 + (k & 1)]
                    = __float2half_rn(s);
            }
        }
        if (tid < NROWS && t + 1 < TSTEPS){
            int row = tid;
            int m = row >> 4, rr = row & 15, hh = rr >> 3, rl = rr & 7;
            __half* hp = (__half*)hWf;
            if (t + 1 < WARM){
                const float* ip = inputs + ((size_t)(row0 + row)*192 + (t + 1))*6;
                #pragma unroll
                for (int k = 0; k < 6; k++)
                    hp[(((m*L1_SLABS + 16)*32 + rl*4 + (k >> 1))*4 + hh)*2 + (k & 1)]
                        = __float2half_rn(ip[k]);
            } else {
                float qv = qpre[row*127 + (t + 1 - WARM)];
                hp[(((m*L1_SLABS + 16)*32 + rl*4)*4 + hh)*2] = __float2half_rn(qv);
            }
        }
        __syncthreads();                       // B3: x_{t+1} visible
    }
}

// ---------------------------------------------------------------------------
extern "C" void kernel_launch(void* const* d_in, const int* in_sizes, int n_in,
                              void* d_out, int out_size) {
    (void)in_sizes; (void)n_in; (void)out_size;
    const float* inputs = (const float*)d_in[0];
    const float* W1 = (const float*)d_in[1];
    const float* U1 = (const float*)d_in[2];
    const float* b1 = (const float*)d_in[3];
    const float* W2 = (const float*)d_in[4];
    const float* U2 = (const float*)d_in[5];
    const float* b2 = (const float*)d_in[6];
    const float* Wd = (const float*)d_in[7];
    const float* bd = (const float*)d_in[8];
    float* out = (float*)d_out;

    cudaFuncSetAttribute(gru_kernel, cudaFuncAttributeMaxDynamicSharedMemorySize,
                         SMEM_BYTES);
    prep_kernel<<<(TOT_U4 + 255)/256, 256>>>(W1, U1, W2, U2);
    gru_kernel<<<NCTA, NTHREADS, SMEM_BYTES>>>(inputs, b1, b2, Wd, bd, out);
}

// round 16
// speedup vs baseline: 1.0763x; 1.0763x over previous
#include <cuda_runtime.h>
#include <cuda_fp16.h>
#include <cstdint>

#define UNITS   256
#define G3      768
#define NROWS   32
#define NCTA    128
#define NTHREADS 512
#define TSTEPS  191
#define WARM    64

#define L1_SLABS 17
#define L2_SLABS 32
#define L1_U4   (L1_SLABS*1536)
#define L2_U4   (L2_SLABS*1536)
#define TOT_U4  (L1_U4 + L2_U4)

__device__ uint4 g_wts[TOT_U4];  // fp16 blobs, fragment-ordered for m16n8k16

#define SZ_HA1  (2*L1_SLABS*32*4)
#define OFF_HA1 0
#define OFF_HA2 (OFF_HA1 + 2*SZ_HA1)
#define SZ_HA2  (2*16*32*4)
#define OFF_H1P (OFF_HA2 + SZ_HA2)          // thread-private h1 state, stride 17
#define SZ_H1P  (NTHREADS*17)
#define OFF_BM1 (OFF_H1P + SZ_H1P)
#define OFF_BM2 (OFF_BM1 + 1024)
#define OFF_WD  (OFF_BM2 + 1024)
#define OFF_BD  (OFF_WD + UNITS*5)
#define OFF_PART (OFF_BD + 8)
#define OFF_QP  (OFF_PART + 16*160)
#define SMEM_FLOATS (OFF_QP + NROWS*127)
#define SMEM_BYTES  (SMEM_FLOATS*4)

__device__ __forceinline__ uint32_t pack2(float lo, float hi){
    __half2 h = __floats2half2_rn(lo, hi);
    return *(uint32_t*)&h;
}
__device__ __forceinline__ void mma_h(float (&c)[4], const uint4& a, uint32_t b0, uint32_t b1){
    asm volatile(
        "mma.sync.aligned.m16n8k16.row.col.f32.f16.f16.f32 "
        "{%0,%1,%2,%3},{%4,%5,%6,%7},{%8,%9},{%0,%1,%2,%3};\n"
        : "+f"(c[0]), "+f"(c[1]), "+f"(c[2]), "+f"(c[3])
        : "r"(a.x), "r"(a.y), "r"(a.z), "r"(a.w), "r"(b0), "r"(b1));
}
__device__ __forceinline__ float tanh_ap(float x){
    float y; asm("tanh.approx.f32 %0, %1;" : "=f"(y) : "f"(x)); return y;
}
__device__ __forceinline__ float sigf(float x){
    return fmaf(tanh_ap(0.5f*x), 0.5f, 0.5f);
}

#define MMA_GATE(ACC, B4, a0, a1) do {                     \
    mma_h(ACC[0][0], a0, (B4).x, (B4).y);                  \
    mma_h(ACC[1][0], a1, (B4).x, (B4).y);                  \
    mma_h(ACC[0][1], a0, (B4).z, (B4).w);                  \
    mma_h(ACC[1][1], a1, (B4).z, (B4).w);                  \
} while (0)

#define ZERO_ACC do {                                      \
    _Pragma("unroll")                                      \
    for (int m_=0;m_<2;m_++) _Pragma("unroll")             \
    for (int t_=0;t_<2;t_++) _Pragma("unroll")             \
    for (int c_=0;c_<4;c_++){                              \
        az[m_][t_][c_]=0.f; ar[m_][t_][c_]=0.f;            \
        axh[m_][t_][c_]=0.f; arh[m_][t_][c_]=0.f; }        \
} while (0)

#define PF_STEP(CZ,CR,CH,Bn) \
    uint4 CZ = pbz0, CR = pbr0, CH = pbh0;                  \
    pbz0 = pbz1; pbr0 = pbr1; pbh0 = pbh1;                  \
    pbz1 = __ldg(Bn); pbr1 = __ldg((Bn)+512); pbh1 = __ldg((Bn)+1024);

// ---------------------------------------------------------------------------
__global__ void prep_kernel(const float* __restrict__ W1, const float* __restrict__ U1,
                            const float* __restrict__ W2, const float* __restrict__ U2){
    for (int idx = blockIdx.x*blockDim.x + threadIdx.x; idx < TOT_U4;
         idx += gridDim.x*blockDim.x){
        int li   = (idx < L1_U4) ? idx : idx - L1_U4;
        int lane = li & 31;
        int w    = (li >> 5) & 7;
        int t2   = (li >> 8) & 1;
        int g    = (li >> 9) % 3;
        int slab = (li >> 9) / 3;
        int lc = lane & 3, lr = lane >> 2;
        uint32_t v[4];
        #pragma unroll
        for (int j = 0; j < 4; j++){
            int q  = j & 1;
            int tt = t2*2 + (j >> 1);
            int col = g*256 + w*32 + tt*8 + lr;
            int kl  = 2*lc + 8*q;
            float s0, s1;
            if (idx < L1_U4){
                if (slab < 16){
                    s0 = U1[(slab*16 + kl)*G3 + col];
                    s1 = U1[(slab*16 + kl + 1)*G3 + col];
                } else {
                    s0 = (kl     < 6) ? W1[kl*G3 + col]       : 0.f;
                    s1 = (kl + 1 < 6) ? W1[(kl + 1)*G3 + col] : 0.f;
                }
            } else {
                if (slab < 16){
                    s0 = W2[(slab*16 + kl)*G3 + col];
                    s1 = W2[(slab*16 + kl + 1)*G3 + col];
                } else {
                    s0 = U2[((slab-16)*16 + kl)*G3 + col];
                    s1 = U2[((slab-16)*16 + kl + 1)*G3 + col];
                }
            }
            v[j] = pack2(s0, s1);
        }
        g_wts[idx] = make_uint4(v[0], v[1], v[2], v[3]);
    }
}

// ---------------------------------------------------------------------------
__global__ void __launch_bounds__(NTHREADS, 1)
gru_kernel(const float* __restrict__ inputs, const float* __restrict__ gb1,
           const float* __restrict__ gb2, const float* __restrict__ gWd,
           const float* __restrict__ gbd, float* __restrict__ out){
    extern __shared__ __align__(16) float sm[];
    float* bm1 = sm + OFF_BM1;
    float* bm2 = sm + OFF_BM2;
    float* wds = sm + OFF_WD;
    float* bds = sm + OFF_BD;
    float* part= sm + OFF_PART;
    float* qpre= sm + OFF_QP;

    const int tid  = threadIdx.x;
    const int lane = tid & 31;
    const int warp = tid >> 5;
    const int lr   = lane >> 2;
    const int lc   = lane & 3;
    const int u0   = warp * 16;
    const int row0 = blockIdx.x * NROWS;
    const int wB   = ((warp & 1) << 8) + ((warp >> 1) << 5) + lane;

    float* h1p = sm + OFF_H1P + tid*17;   // conflict-free thread-private h1 state

    // merged biases: [0:256)=z, [256:512)=r, [512:768)=xh, [768:1024)=rh
    for (int i = tid; i < 256; i += NTHREADS){
        bm1[i]       = gb1[i]       + gb1[G3 + i];
        bm1[256 + i] = gb1[256 + i] + gb1[G3 + 256 + i];
        bm1[512 + i] = gb1[512 + i];
        bm1[768 + i] = gb1[G3 + 512 + i];
        bm2[i]       = gb2[i]       + gb2[G3 + i];
        bm2[256 + i] = gb2[256 + i] + gb2[G3 + 256 + i];
        bm2[512 + i] = gb2[512 + i];
        bm2[768 + i] = gb2[G3 + 512 + i];
    }
    for (int i = tid; i < UNITS*5; i += NTHREADS) wds[i] = gWd[i];
    if (tid < 5) bds[tid] = gbd[tid];
    for (int i = tid; i < 2*SZ_HA1; i += NTHREADS) sm[OFF_HA1 + i] = 0.f;
    for (int i = tid; i < SZ_HA2;   i += NTHREADS) sm[OFF_HA2 + i] = 0.f;
    #pragma unroll
    for (int i = 0; i < 16; i++) h1p[i] = 0.f;
    for (int i = tid; i < NROWS*127; i += NTHREADS){
        int row = i / 127, s = i % 127;
        qpre[i] = inputs[((size_t)(row0 + row)*192 + WARM + s)*6];
    }
    __syncthreads();

    // stage x_0 into buffer 0, slab 16
    if (tid < NROWS){
        int row = tid;
        const float* ip = inputs + ((size_t)(row0 + row)*192 + 0)*6;
        int m = row >> 4, rr = row & 15, hh = rr >> 3, rl = rr & 7;
        __half* hp = (__half*)(sm + OFF_HA1);
        #pragma unroll
        for (int k = 0; k < 6; k++)
            hp[(((m*L1_SLABS + 16)*32 + rl*4 + (k >> 1))*4 + hh)*2 + (k & 1)]
                = __float2half_rn(ip[k]);
    }
    __syncthreads();

    const uint4* hA2u = (const uint4*)(sm + OFF_HA2);
    const uint4* B1b  = g_wts + wB;
    const uint4* B2b  = g_wts + L1_U4 + wB;

    float az[2][2][4], ar[2][2][4], axh[2][2][4], arh[2][2][4];
    float h2s[16];                 // layer-2 state, exact fp32, thread-private regs
    #pragma unroll
    for (int i = 0; i < 16; i++) h2s[i] = 0.f;
    #define HIDX(m,tt,hi,cc) ((((m)*2+(tt))*2+(hi))*2+(cc))

    uint4 pbz0 = __ldg(B1b),        pbr0 = __ldg(B1b + 512),        pbh0 = __ldg(B1b + 1024);
    uint4 pbz1 = __ldg(B1b + 1536), pbr1 = __ldg(B1b + 1536 + 512), pbh1 = __ldg(B1b + 1536 + 1024);

    for (int t = 0; t < TSTEPS; t++){
        const int p = t & 1;
        const uint4* hAr = (const uint4*)(sm + OFF_HA1 + p*SZ_HA1);
        float*       hWf = sm + OFF_HA1 + (1-p)*SZ_HA1;
        const uint4* hAw = (const uint4*)hWf;

        // ===== GEMM1: h1_old @ U1 (slabs 0..15) + x (slab 16) =====
        ZERO_ACC;
        #pragma unroll 4
        for (int s = 0; s < 16; s++){
            uint4 a0 = hAr[s*32 + lane];
            uint4 a1 = hAr[(L1_SLABS + s)*32 + lane];
            const uint4* Bn = (s <= 14) ? (B1b + (s+2)*1536) : (B2b + 16*1536);
            PF_STEP(cz, cr, ch, Bn);
            MMA_GATE(az,  cz, a0, a1);
            MMA_GATE(ar,  cr, a0, a1);
            MMA_GATE(arh, ch, a0, a1);
        }
        {
            uint4 a0 = hAr[16*32 + lane];
            uint4 a1 = hAr[(L1_SLABS + 16)*32 + lane];
            const uint4* Bn = B2b + 17*1536;
            PF_STEP(cz, cr, ch, Bn);
            MMA_GATE(az,  cz, a0, a1);
            MMA_GATE(ar,  cr, a0, a1);
            MMA_GATE(axh, ch, a0, a1);
        }

        // ---- gate 1 (thread-private smem state, conflict-free) + h1 A-store ----
        {
            uint32_t* wp = (uint32_t*)hWf;
            #pragma unroll
            for (int tt = 0; tt < 2; tt++){
                int uc0 = u0 + tt*8 + 2*lc, uc1 = uc0 + 1;
                float bz0 = bm1[uc0],       bz1 = bm1[uc1];
                float br0 = bm1[256 + uc0], br1 = bm1[256 + uc1];
                float bx0 = bm1[512 + uc0], bx1 = bm1[512 + uc1];
                float bh0 = bm1[768 + uc0], bh1 = bm1[768 + uc1];
                #pragma unroll
                for (int m = 0; m < 2; m++)
                    #pragma unroll
                    for (int hi = 0; hi < 2; hi++){
                        int c0 = hi*2, c1 = hi*2 + 1;
                        float z0 = sigf(az[m][tt][c0] + bz0);
                        float r0 = sigf(ar[m][tt][c0] + br0);
                        float g0 = tanh_ap(axh[m][tt][c0] + bx0 + r0*(arh[m][tt][c0] + bh0));
                        float v0 = z0*h1p[HIDX(m,tt,hi,0)] + (1.f - z0)*g0;
                        h1p[HIDX(m,tt,hi,0)] = v0;
                        float z1 = sigf(az[m][tt][c1] + bz1);
                        float r1 = sigf(ar[m][tt][c1] + br1);
                        float g1 = tanh_ap(axh[m][tt][c1] + bx1 + r1*(arh[m][tt][c1] + bh1));
                        float v1 = z1*h1p[HIDX(m,tt,hi,1)] + (1.f - z1)*g1;
                        h1p[HIDX(m,tt,hi,1)] = v1;
                        wp[((m*L1_SLABS + warp)*32 + lr*4 + lc)*4 + tt*2 + hi]
                            = pack2(v0, v1);
                    }
            }
        }

        // ===== GEMM2a: h2_old @ U2 (L2 blob slabs 16..31) =====
        ZERO_ACC;
        #pragma unroll 4
        for (int s = 0; s < 16; s++){
            uint4 a0 = hA2u[s*32 + lane];
            uint4 a1 = hA2u[(16 + s)*32 + lane];
            const uint4* Bn = (s <= 13) ? (B2b + (18 + s)*1536)
                             : ((s == 14) ? B2b : (B2b + 1536));
            PF_STEP(cz, cr, ch, Bn);
            MMA_GATE(az,  cz, a0, a1);
            MMA_GATE(ar,  cr, a0, a1);
            MMA_GATE(arh, ch, a0, a1);
        }
        __syncthreads();                       // B1: h1_new visible

        // ===== GEMM2b: h1_new @ W2 (L2 blob slabs 0..15) =====
        #pragma unroll 4
        for (int s = 0; s < 16; s++){
            uint4 a0 = hAw[s*32 + lane];
            uint4 a1 = hAw[(L1_SLABS + s)*32 + lane];
            const uint4* Bn = (s <= 13) ? (B2b + (s+2)*1536)
                             : ((s == 14) ? B1b : (B1b + 1536));
            PF_STEP(cz, cr, ch, Bn);
            MMA_GATE(az,  cz, a0, a1);
            MMA_GATE(ar,  cr, a0, a1);
            MMA_GATE(axh, ch, a0, a1);
        }

        // ---- gate 2 (register state) + inline h2 A-store + pred partials ----
        float ps[4][5];
        #pragma unroll
        for (int ri = 0; ri < 4; ri++)
            #pragma unroll
            for (int o = 0; o < 5; o++) ps[ri][o] = 0.f;
        {
            uint32_t* wp = (uint32_t*)(sm + OFF_HA2);
            #pragma unroll
            for (int tt = 0; tt < 2; tt++){
                int uc0 = u0 + tt*8 + 2*lc, uc1 = uc0 + 1;
                float bz0 = bm2[uc0],       bz1 = bm2[uc1];
                float br0 = bm2[256 + uc0], br1 = bm2[256 + uc1];
                float bx0 = bm2[512 + uc0], bx1 = bm2[512 + uc1];
                float bh0 = bm2[768 + uc0], bh1 = bm2[768 + uc1];
                float wd0[5], wd1[5];
                #pragma unroll
                for (int o = 0; o < 5; o++){ wd0[o] = wds[uc0*5 + o]; wd1[o] = wds[uc1*5 + o]; }
                #pragma unroll
                for (int m = 0; m < 2; m++)
                    #pragma unroll
                    for (int hi = 0; hi < 2; hi++){
                        int c0 = hi*2, c1 = hi*2 + 1;
                        float z0 = sigf(az[m][tt][c0] + bz0);
                        float r0 = sigf(ar[m][tt][c0] + br0);
                        float g0 = tanh_ap(axh[m][tt][c0] + bx0 + r0*(arh[m][tt][c0] + bh0));
                        float v0 = z0*h2s[HIDX(m,tt,hi,0)] + (1.f - z0)*g0;
                        h2s[HIDX(m,tt,hi,0)] = v0;
                        float z1 = sigf(az[m][tt][c1] + bz1);
                        float r1 = sigf(ar[m][tt][c1] + br1);
                        float g1 = tanh_ap(axh[m][tt][c1] + bx1 + r1*(arh[m][tt][c1] + bh1));
                        float v1 = z1*h2s[HIDX(m,tt,hi,1)] + (1.f - z1)*g1;
                        h2s[HIDX(m,tt,hi,1)] = v1;
                        wp[((m*16 + warp)*32 + lr*4 + lc)*4 + tt*2 + hi]
                            = pack2(v0, v1);
                        int ri = 2*m + hi;
                        #pragma unroll
                        for (int o = 0; o < 5; o++)
                            ps[ri][o] += v0*wd0[o] + v1*wd1[o];
                    }
            }
        }
        #pragma unroll
        for (int ri = 0; ri < 4; ri++)
            #pragma unroll
            for (int o = 0; o < 5; o++){
                ps[ri][o] += __shfl_xor_sync(0xffffffffu, ps[ri][o], 1);
                ps[ri][o] += __shfl_xor_sync(0xffffffffu, ps[ri][o], 2);
            }
        if (lc == 0){
            #pragma unroll
            for (int ri = 0; ri < 4; ri++)
                #pragma unroll
                for (int o = 0; o < 5; o++)
                    part[warp*160 + (lr + 8*ri)*5 + o] = ps[ri][o];
        }
        __syncthreads();                       // B2

        // ---- tail: reduce, output, stage x_{t+1} ----
        if (tid < 160){
            int row = tid / 5, o = tid % 5;
            float s = bds[o];
            #pragma unroll
            for (int w = 0; w < 16; w++) s += part[w*160 + tid];
            int grow = row0 + row;
            int tout = (t < WARM) ? t : t + 1;
            out[(size_t)grow*960 + tout*5 + o] = s;
            if (t == WARM - 1) out[(size_t)grow*960 + WARM*5 + o] = s;
            if (t + 1 >= WARM && t + 1 < TSTEPS){
                int k = o + 1;
                int m = row >> 4, rr = row & 15, hh = rr >> 3, rl = rr & 7;
                __half* hp = (__half*)hWf;
                hp[(((m*L1_SLABS + 16)*32 + rl*4 + (k >> 1))*4 + hh)*2 + (k & 1)]
                    = __float2half_rn(s);
            }
        }
        if (tid < NROWS && t + 1 < TSTEPS){
            int row = tid;
            int m = row >> 4, rr = row & 15, hh = rr >> 3, rl = rr & 7;
            __half* hp = (__half*)hWf;
            if (t + 1 < WARM){
                const float* ip = inputs + ((size_t)(row0 + row)*192 + (t + 1))*6;
                #pragma unroll
                for (int k = 0; k < 6; k++)
                    hp[(((m*L1_SLABS + 16)*32 + rl*4 + (k >> 1))*4 + hh)*2 + (k & 1)]
                        = __float2half_rn(ip[k]);
            } else {
                float qv = qpre[row*127 + (t + 1 - WARM)];
                hp[(((m*L1_SLABS + 16)*32 + rl*4)*4 + hh)*2] = __float2half_rn(qv);
            }
        }
        __syncthreads();                       // B3: x_{t+1} visible
    }
}

// ---------------------------------------------------------------------------
extern "C" void kernel_launch(void* const* d_in, const int* in_sizes, int n_in,
                              void* d_out, int out_size) {
    (void)in_sizes; (void)n_in; (void)out_size;
    const float* inputs = (const float*)d_in[0];
    const float* W1 = (const float*)d_in[1];
    const float* U1 = (const float*)d_in[2];
    const float* b1 = (const float*)d_in[3];
    const float* W2 = (const float*)d_in[4];
    const float* U2 = (const float*)d_in[5];
    const float* b2 = (const float*)d_in[6];
    const float* Wd = (const float*)d_in[7];
    const float* bd = (const float*)d_in[8];
    float* out = (float*)d_out;

    cudaFuncSetAttribute(gru_kernel, cudaFuncAttributeMaxDynamicSharedMemorySize,
                         SMEM_BYTES);
    prep_kernel<<<(TOT_U4 + 255)/256, 256>>>(W1, U1, W2, U2);
    gru_kernel<<<NCTA, NTHREADS, SMEM_BYTES>>>(inputs, b1, b2, Wd, bd, out);
}

// round 17
// speedup vs baseline: 1.0967x; 1.0189x over previous
#include <cuda_runtime.h>
#include <cuda_fp16.h>
#include <cstdint>

#define UNITS   256
#define G3      768
#define NROWS   32
#define NCTA    128
#define NTHREADS 512
#define TSTEPS  191
#define WARM    64
#define HFS     260

#define L1_SLABS 17
#define L2_SLABS 32
#define L1_U4   (L1_SLABS*1536)
#define L2_U4   (L2_SLABS*1536)
#define TOT_U4  (L1_U4 + L2_U4)

__device__ uint4 g_wts[TOT_U4];  // fp16 blobs, fragment-ordered for m16n8k16

#define SZ_HA1  (2*L1_SLABS*32*4)
#define OFF_HA1 0
#define OFF_HA2 (OFF_HA1 + 2*SZ_HA1)
#define SZ_HA2  (2*16*32*4)
#define OFF_HF1 (OFF_HA2 + SZ_HA2)
#define OFF_BM1 (OFF_HF1 + NROWS*HFS)
#define OFF_BM2 (OFF_BM1 + 1024)
#define OFF_WD  (OFF_BM2 + 1024)
#define OFF_BD  (OFF_WD + UNITS*5)
#define OFF_PART (OFF_BD + 8)
#define OFF_QP  (OFF_PART + 16*160)
#define SMEM_FLOATS (OFF_QP + NROWS*127)
#define SMEM_BYTES  (SMEM_FLOATS*4)

__device__ __forceinline__ uint32_t pack2(float lo, float hi){
    __half2 h = __floats2half2_rn(lo, hi);
    return *(uint32_t*)&h;
}
__device__ __forceinline__ void mma_h(float (&c)[4], const uint4& a, uint32_t b0, uint32_t b1){
    asm volatile(
        "mma.sync.aligned.m16n8k16.row.col.f32.f16.f16.f32 "
        "{%0,%1,%2,%3},{%4,%5,%6,%7},{%8,%9},{%0,%1,%2,%3};\n"
        : "+f"(c[0]), "+f"(c[1]), "+f"(c[2]), "+f"(c[3])
        : "r"(a.x), "r"(a.y), "r"(a.z), "r"(a.w), "r"(b0), "r"(b1));
}
__device__ __forceinline__ float tanh_ap(float x){
    float y; asm("tanh.approx.f32 %0, %1;" : "=f"(y) : "f"(x)); return y;
}
__device__ __forceinline__ float sigf(float x){
    return fmaf(tanh_ap(0.5f*x), 0.5f, 0.5f);
}

#define MMA_GATE(ACC, B4, a0, a1) do {                     \
    mma_h(ACC[0][0], a0, (B4).x, (B4).y);                  \
    mma_h(ACC[1][0], a1, (B4).x, (B4).y);                  \
    mma_h(ACC[0][1], a0, (B4).z, (B4).w);                  \
    mma_h(ACC[1][1], a1, (B4).z, (B4).w);                  \
} while (0)

#define ZERO_ACC do {                                      \
    _Pragma("unroll")                                      \
    for (int m_=0;m_<2;m_++) _Pragma("unroll")             \
    for (int t_=0;t_<2;t_++) _Pragma("unroll")             \
    for (int c_=0;c_<4;c_++){                              \
        az[m_][t_][c_]=0.f; ar[m_][t_][c_]=0.f;            \
        axh[m_][t_][c_]=0.f; arh[m_][t_][c_]=0.f; }        \
} while (0)

#define PF_STEP(CZ,CR,CH,Bn) \
    uint4 CZ = pbz0, CR = pbr0, CH = pbh0;                  \
    pbz0 = pbz1; pbr0 = pbr1; pbh0 = pbh1;                  \
    pbz1 = __ldg(Bn); pbr1 = __ldg((Bn)+512); pbh1 = __ldg((Bn)+1024);

// ---------------------------------------------------------------------------
__global__ void prep_kernel(const float* __restrict__ W1, const float* __restrict__ U1,
                            const float* __restrict__ W2, const float* __restrict__ U2){
    for (int idx = blockIdx.x*blockDim.x + threadIdx.x; idx < TOT_U4;
         idx += gridDim.x*blockDim.x){
        int li   = (idx < L1_U4) ? idx : idx - L1_U4;
        int lane = li & 31;
        int w    = (li >> 5) & 7;
        int t2   = (li >> 8) & 1;
        int g    = (li >> 9) % 3;
        int slab = (li >> 9) / 3;
        int lc = lane & 3, lr = lane >> 2;
        uint32_t v[4];
        #pragma unroll
        for (int j = 0; j < 4; j++){
            int q  = j & 1;
            int tt = t2*2 + (j >> 1);
            int col = g*256 + w*32 + tt*8 + lr;
            int kl  = 2*lc + 8*q;
            float s0, s1;
            if (idx < L1_U4){
                if (slab < 16){
                    s0 = U1[(slab*16 + kl)*G3 + col];
                    s1 = U1[(slab*16 + kl + 1)*G3 + col];
                } else {
                    s0 = (kl     < 6) ? W1[kl*G3 + col]       : 0.f;
                    s1 = (kl + 1 < 6) ? W1[(kl + 1)*G3 + col] : 0.f;
                }
            } else {
                if (slab < 16){
                    s0 = W2[(slab*16 + kl)*G3 + col];
                    s1 = W2[(slab*16 + kl + 1)*G3 + col];
                } else {
                    s0 = U2[((slab-16)*16 + kl)*G3 + col];
                    s1 = U2[((slab-16)*16 + kl + 1)*G3 + col];
                }
            }
            v[j] = pack2(s0, s1);
        }
        g_wts[idx] = make_uint4(v[0], v[1], v[2], v[3]);
    }
}

// ---------------------------------------------------------------------------
__global__ void __launch_bounds__(NTHREADS, 1)
gru_kernel(const float* __restrict__ inputs, const float* __restrict__ gb1,
           const float* __restrict__ gb2, const float* __restrict__ gWd,
           const float* __restrict__ gbd, float* __restrict__ out){
    extern __shared__ __align__(16) float sm[];
    float* hF1 = sm + OFF_HF1;
    float* bm1 = sm + OFF_BM1;
    float* bm2 = sm + OFF_BM2;
    float* wds = sm + OFF_WD;
    float* bds = sm + OFF_BD;
    float* part= sm + OFF_PART;
    float* qpre= sm + OFF_QP;

    const int tid  = threadIdx.x;
    const int lane = tid & 31;
    const int warp = tid >> 5;
    const int lr   = lane >> 2;
    const int lc   = lane & 3;
    const int u0   = warp * 16;
    const int row0 = blockIdx.x * NROWS;
    const int wB   = ((warp & 1) << 8) + ((warp >> 1) << 5) + lane;

    // merged biases: [0:256)=z, [256:512)=r, [512:768)=xh, [768:1024)=rh
    for (int i = tid; i < 256; i += NTHREADS){
        bm1[i]       = gb1[i]       + gb1[G3 + i];
        bm1[256 + i] = gb1[256 + i] + gb1[G3 + 256 + i];
        bm1[512 + i] = gb1[512 + i];
        bm1[768 + i] = gb1[G3 + 512 + i];
        bm2[i]       = gb2[i]       + gb2[G3 + i];
        bm2[256 + i] = gb2[256 + i] + gb2[G3 + 256 + i];
        bm2[512 + i] = gb2[512 + i];
        bm2[768 + i] = gb2[G3 + 512 + i];
    }
    for (int i = tid; i < UNITS*5; i += NTHREADS) wds[i] = gWd[i];
    if (tid < 5) bds[tid] = gbd[tid];
    for (int i = tid; i < 2*SZ_HA1; i += NTHREADS) sm[OFF_HA1 + i] = 0.f;
    for (int i = tid; i < SZ_HA2;   i += NTHREADS) sm[OFF_HA2 + i] = 0.f;
    for (int i = tid; i < NROWS*HFS; i += NTHREADS) hF1[i] = 0.f;
    for (int i = tid; i < NROWS*127; i += NTHREADS){
        int row = i / 127, s = i % 127;
        qpre[i] = inputs[((size_t)(row0 + row)*192 + WARM + s)*6];
    }
    __syncthreads();

    // stage x_0 into buffer 0, slab 16
    if (tid < NROWS){
        int row = tid;
        const float* ip = inputs + ((size_t)(row0 + row)*192 + 0)*6;
        int m = row >> 4, rr = row & 15, hh = rr >> 3, rl = rr & 7;
        __half* hp = (__half*)(sm + OFF_HA1);
        #pragma unroll
        for (int k = 0; k < 6; k++)
            hp[(((m*L1_SLABS + 16)*32 + rl*4 + (k >> 1))*4 + hh)*2 + (k & 1)]
                = __float2half_rn(ip[k]);
    }
    __syncthreads();

    const uint4* hA2u = (const uint4*)(sm + OFF_HA2);
    const uint4* B1b  = g_wts + wB;
    const uint4* B2b  = g_wts + L1_U4 + wB;

    float az[2][2][4], ar[2][2][4], axh[2][2][4], arh[2][2][4];
    float h2s[16];                 // layer-2 state, exact fp32, thread-private
    #pragma unroll
    for (int i = 0; i < 16; i++) h2s[i] = 0.f;
    #define HIDX(m,tt,hi,cc) ((((m)*2+(tt))*2+(hi))*2+(cc))

    uint4 pbz0 = __ldg(B1b),        pbr0 = __ldg(B1b + 512),        pbh0 = __ldg(B1b + 1024);
    uint4 pbz1 = __ldg(B1b + 1536), pbr1 = __ldg(B1b + 1536 + 512), pbh1 = __ldg(B1b + 1536 + 1024);

    for (int t = 0; t < TSTEPS; t++){
        const int p = t & 1;
        const uint4* hAr = (const uint4*)(sm + OFF_HA1 + p*SZ_HA1);
        float*       hWf = sm + OFF_HA1 + (1-p)*SZ_HA1;
        const uint4* hAw = (const uint4*)hWf;

        // ===== GEMM1: h1_old @ U1 (slabs 0..15) + x (slab 16) =====
        ZERO_ACC;
        #pragma unroll
        for (int s = 0; s < 16; s++){
            uint4 a0 = hAr[s*32 + lane];
            uint4 a1 = hAr[(L1_SLABS + s)*32 + lane];
            const uint4* Bn = (s <= 14) ? (B1b + (s+2)*1536) : (B2b + 16*1536);
            PF_STEP(cz, cr, ch, Bn);
            MMA_GATE(az,  cz, a0, a1);
            MMA_GATE(ar,  cr, a0, a1);
            MMA_GATE(arh, ch, a0, a1);
        }
        {
            uint4 a0 = hAr[16*32 + lane];
            uint4 a1 = hAr[(L1_SLABS + 16)*32 + lane];
            const uint4* Bn = B2b + 17*1536;
            PF_STEP(cz, cr, ch, Bn);
            MMA_GATE(az,  cz, a0, a1);
            MMA_GATE(ar,  cr, a0, a1);
            MMA_GATE(axh, ch, a0, a1);
        }

        // ---- gate 1 (fp32 smem state) + inline h1_new A-store ----
        {
            uint32_t* wp = (uint32_t*)hWf;
            #pragma unroll
            for (int tt = 0; tt < 2; tt++){
                int uc0 = u0 + tt*8 + 2*lc, uc1 = uc0 + 1;
                float bz0 = bm1[uc0],       bz1 = bm1[uc1];
                float br0 = bm1[256 + uc0], br1 = bm1[256 + uc1];
                float bx0 = bm1[512 + uc0], bx1 = bm1[512 + uc1];
                float bh0 = bm1[768 + uc0], bh1 = bm1[768 + uc1];
                #pragma unroll
                for (int m = 0; m < 2; m++)
                    #pragma unroll
                    for (int hi = 0; hi < 2; hi++){
                        int c0 = hi*2, c1 = hi*2 + 1;
                        int row = 16*m + lr + 8*hi;
                        float z0 = sigf(az[m][tt][c0] + bz0);
                        float r0 = sigf(ar[m][tt][c0] + br0);
                        float g0 = tanh_ap(axh[m][tt][c0] + bx0 + r0*(arh[m][tt][c0] + bh0));
                        float v0 = z0*hF1[row*HFS + uc0] + (1.f - z0)*g0;
                        hF1[row*HFS + uc0] = v0;
                        float z1 = sigf(az[m][tt][c1] + bz1);
                        float r1 = sigf(ar[m][tt][c1] + br1);
                        float g1 = tanh_ap(axh[m][tt][c1] + bx1 + r1*(arh[m][tt][c1] + bh1));
                        float v1 = z1*hF1[row*HFS + uc1] + (1.f - z1)*g1;
                        hF1[row*HFS + uc1] = v1;
                        wp[((m*L1_SLABS + warp)*32 + lr*4 + lc)*4 + tt*2 + hi]
                            = pack2(v0, v1);
                    }
            }
        }

        // ===== GEMM2a: h2_old @ U2 (L2 blob slabs 16..31) =====
        ZERO_ACC;
        #pragma unroll
        for (int s = 0; s < 16; s++){
            uint4 a0 = hA2u[s*32 + lane];
            uint4 a1 = hA2u[(16 + s)*32 + lane];
            const uint4* Bn = (s <= 13) ? (B2b + (18 + s)*1536)
                             : ((s == 14) ? B2b : (B2b + 1536));
            PF_STEP(cz, cr, ch, Bn);
            MMA_GATE(az,  cz, a0, a1);
            MMA_GATE(ar,  cr, a0, a1);
            MMA_GATE(arh, ch, a0, a1);
        }
        __syncthreads();                       // B1: h1_new visible

        // ===== GEMM2b: h1_new @ W2 (L2 blob slabs 0..15) =====
        #pragma unroll
        for (int s = 0; s < 16; s++){
            uint4 a0 = hAw[s*32 + lane];
            uint4 a1 = hAw[(L1_SLABS + s)*32 + lane];
            const uint4* Bn = (s <= 13) ? (B2b + (s+2)*1536)
                             : ((s == 14) ? B1b : (B1b + 1536));
            PF_STEP(cz, cr, ch, Bn);
            MMA_GATE(az,  cz, a0, a1);
            MMA_GATE(ar,  cr, a0, a1);
            MMA_GATE(axh, ch, a0, a1);
        }

        // ---- gate 2 (register state) + inline h2 A-store + pred partials ----
        float ps[4][5];
        #pragma unroll
        for (int ri = 0; ri < 4; ri++)
            #pragma unroll
            for (int o = 0; o < 5; o++) ps[ri][o] = 0.f;
        {
            uint32_t* wp = (uint32_t*)(sm + OFF_HA2);
            #pragma unroll
            for (int tt = 0; tt < 2; tt++){
                int uc0 = u0 + tt*8 + 2*lc, uc1 = uc0 + 1;
                float bz0 = bm2[uc0],       bz1 = bm2[uc1];
                float br0 = bm2[256 + uc0], br1 = bm2[256 + uc1];
                float bx0 = bm2[512 + uc0], bx1 = bm2[512 + uc1];
                float bh0 = bm2[768 + uc0], bh1 = bm2[768 + uc1];
                float wd0[5], wd1[5];
                #pragma unroll
                for (int o = 0; o < 5; o++){ wd0[o] = wds[uc0*5 + o]; wd1[o] = wds[uc1*5 + o]; }
                #pragma unroll
                for (int m = 0; m < 2; m++)
                    #pragma unroll
                    for (int hi = 0; hi < 2; hi++){
                        int c0 = hi*2, c1 = hi*2 + 1;
                        float z0 = sigf(az[m][tt][c0] + bz0);
                        float r0 = sigf(ar[m][tt][c0] + br0);
                        float g0 = tanh_ap(axh[m][tt][c0] + bx0 + r0*(arh[m][tt][c0] + bh0));
                        float v0 = z0*h2s[HIDX(m,tt,hi,0)] + (1.f - z0)*g0;
                        h2s[HIDX(m,tt,hi,0)] = v0;
                        float z1 = sigf(az[m][tt][c1] + bz1);
                        float r1 = sigf(ar[m][tt][c1] + br1);
                        float g1 = tanh_ap(axh[m][tt][c1] + bx1 + r1*(arh[m][tt][c1] + bh1));
                        float v1 = z1*h2s[HIDX(m,tt,hi,1)] + (1.f - z1)*g1;
                        h2s[HIDX(m,tt,hi,1)] = v1;
                        wp[((m*16 + warp)*32 + lr*4 + lc)*4 + tt*2 + hi]
                            = pack2(v0, v1);
                        int ri = 2*m + hi;
                        #pragma unroll
                        for (int o = 0; o < 5; o++)
                            ps[ri][o] += v0*wd0[o] + v1*wd1[o];
                    }
            }
        }
        #pragma unroll
        for (int ri = 0; ri < 4; ri++)
            #pragma unroll
            for (int o = 0; o < 5; o++){
                ps[ri][o] += __shfl_xor_sync(0xffffffffu, ps[ri][o], 1);
                ps[ri][o] += __shfl_xor_sync(0xffffffffu, ps[ri][o], 2);
            }
        if (lc == 0){
            #pragma unroll
            for (int ri = 0; ri < 4; ri++)
                #pragma unroll
                for (int o = 0; o < 5; o++)
                    part[warp*160 + (lr + 8*ri)*5 + o] = ps[ri][o];
        }
        __syncthreads();                       // B2

        // ---- tail: reduce, output, stage x_{t+1} ----
        if (tid < 160){
            int row = tid / 5, o = tid % 5;
            float s = bds[o];
            #pragma unroll
            for (int w = 0; w < 16; w++) s += part[w*160 + tid];
            int grow = row0 + row;
            int tout = (t < WARM) ? t : t + 1;
            out[(size_t)grow*960 + tout*5 + o] = s;
            if (t == WARM - 1) out[(size_t)grow*960 + WARM*5 + o] = s;
            if (t + 1 >= WARM && t + 1 < TSTEPS){
                int k = o + 1;
                int m = row >> 4, rr = row & 15, hh = rr >> 3, rl = rr & 7;
                __half* hp = (__half*)hWf;
                hp[(((m*L1_SLABS + 16)*32 + rl*4 + (k >> 1))*4 + hh)*2 + (k & 1)]
                    = __float2half_rn(s);
            }
        }
        if (tid < NROWS && t + 1 < TSTEPS){
            int row = tid;
            int m = row >> 4, rr = row & 15, hh = rr >> 3, rl = rr & 7;
            __half* hp = (__half*)hWf;
            if (t + 1 < WARM){
                const float* ip = inputs + ((size_t)(row0 + row)*192 + (t + 1))*6;
                #pragma unroll
                for (int k = 0; k < 6; k++)
                    hp[(((m*L1_SLABS + 16)*32 + rl*4 + (k >> 1))*4 + hh)*2 + (k & 1)]
                        = __float2half_rn(ip[k]);
            } else {
                float qv = qpre[row*127 + (t + 1 - WARM)];
                hp[(((m*L1_SLABS + 16)*32 + rl*4)*4 + hh)*2] = __float2half_rn(qv);
            }
        }
        __syncthreads();                       // B3: x_{t+1} visible
    }
}

// ---------------------------------------------------------------------------
extern "C" void kernel_launch(void* const* d_in, const int* in_sizes, int n_in,
                              void* d_out, int out_size) {
    (void)in_sizes; (void)n_in; (void)out_size;
    const float* inputs = (const float*)d_in[0];
    const float* W1 = (const float*)d_in[1];
    const float* U1 = (const float*)d_in[2];
    const float* b1 = (const float*)d_in[3];
    const float* W2 = (const float*)d_in[4];
    const float* U2 = (const float*)d_in[5];
    const float* b2 = (const float*)d_in[6];
    const float* Wd = (const float*)d_in[7];
    const float* bd = (const float*)d_in[8];
    float* out = (float*)d_out;

    cudaFuncSetAttribute(gru_kernel, cudaFuncAttributeMaxDynamicSharedMemorySize,
                         SMEM_BYTES);
    prep_kernel<<<(TOT_U4 + 255)/256, 256>>>(W1, U1, W2, U2);
    gru_kernel<<<NCTA, NTHREADS, SMEM_BYTES>>>(inputs, b1, b2, Wd, bd, out);
}